// round 7
// baseline (speedup 1.0000x reference)
#include <cuda_runtime.h>
#include <cstdint>

// ---------------- scratch (static device globals; no allocation) ----------------
__device__ float d_h1[8 * 256 * 1024];      // after dup conv  (8MB)
__device__ float d_h2[8 * 64 * 2048];       // after c1 conv   (4MB)
__device__ float d_xx[8 * 2048];            // per-point squared norms
__device__ float d_g1[8 * 64];              // global max feature
__device__ float d_g2[8 * 128];             // after g-path MLP
__device__ int   d_idx[8 * 2048 * 4];       // top-4 neighbor indices
__device__ float d_feat[8 * 64 * 8192];     // gathered nb features (16MB)
__device__ float d_fa[8 * 64 * 8192];       // ping              (16MB)
__device__ float d_fb[8 * 64 * 8192];       // pong              (16MB)
__device__ float d_local[8 * 64 * 2048];    // max over k        (4MB)
__device__ float d_h4[8 * 256 * 2048];      // head hidden       (16MB)
__device__ float d_T[8 * 64 * 2048];        // ctr-term for conv2a (4MB)
__device__ float d_gb[8 * 256];             // per-(b,o) folded head bias
__device__ float d_W4a_c[256 * 64];         // W4a[:,0:64] compact
__device__ float d_W2a_nb[64 * 64];         // W2a[:,0:64] compact
__device__ float d_W2a_diff[64 * 64];       // W2a[:,64:128]-W2a[:,0:64]
// 3xTF32 pairwise operands: [b][p][72] (K = 64 feat + 1 aug + 7 zero-pad)
__device__ float d_pa_hi[8 * 2048 * 72];    // a = [2h, -1]  hi (tf32)
__device__ float d_pa_lo[8 * 2048 * 72];    // a lo (tf32)
__device__ float d_pb_hi[8 * 2048 * 72];    // b = [h, xx]   hi (tf32)
__device__ float d_pb_lo[8 * 2048 * 72];    // b lo (tf32)

// ---------------- weight repack ----------------
__global__ void prep_weights(const float* __restrict__ W4a,
                             const float* __restrict__ W2a)
{
    int t = blockIdx.x * blockDim.x + threadIdx.x;
    if (t < 16384) {
        int o = t >> 6, c = t & 63;
        d_W4a_c[t] = W4a[o * 192 + c];
    } else if (t < 16384 + 4096) {
        int i = t - 16384;
        int o = i >> 6, c = i & 63;
        d_W2a_nb[i]   = W2a[o * 128 + c];
        d_W2a_diff[i] = W2a[o * 128 + 64 + c] - W2a[o * 128 + c];
    }
}

// =====================================================================
// GEMM A: 128(O) x 128(N) tile, 256 threads, 8x8 micro-tile, Ktile 16.
// =====================================================================
__global__ void __launch_bounds__(256) gemmA(
    const float* __restrict__ A, const float* __restrict__ B, float* __restrict__ C,
    const float* __restrict__ scale, const float* __restrict__ bias,
    int K, int N, long sB, long sC, long sBias)
{
    __shared__ float As[16][128];
    __shared__ float Bs[16][128];
    const float* Bp = B + (long)blockIdx.z * sB;
    float* Cp = C + (long)blockIdx.z * sC;
    const float* biasp = bias + (long)blockIdx.z * sBias;
    const int o0 = blockIdx.y * 128;
    const int n0 = blockIdx.x * 128;
    const int tid = threadIdx.x;
    const int tx = tid & 15, ty = tid >> 4;

    const int ar = tid >> 1;
    const int aq = (tid & 1) * 8;
    const int bk = tid >> 4;
    const int bn = (tid & 15) * 8;

    float acc[8][8];
#pragma unroll
    for (int i = 0; i < 8; ++i)
#pragma unroll
        for (int j = 0; j < 8; ++j) acc[i][j] = 0.f;

    for (int k0 = 0; k0 < K; k0 += 16) {
        float4 a0 = *(const float4*)&A[(long)(o0 + ar) * K + k0 + aq];
        float4 a1 = *(const float4*)&A[(long)(o0 + ar) * K + k0 + aq + 4];
        As[aq + 0][ar] = a0.x; As[aq + 1][ar] = a0.y;
        As[aq + 2][ar] = a0.z; As[aq + 3][ar] = a0.w;
        As[aq + 4][ar] = a1.x; As[aq + 5][ar] = a1.y;
        As[aq + 6][ar] = a1.z; As[aq + 7][ar] = a1.w;
        *(float4*)&Bs[bk][bn]     = *(const float4*)&Bp[(long)(k0 + bk) * N + n0 + bn];
        *(float4*)&Bs[bk][bn + 4] = *(const float4*)&Bp[(long)(k0 + bk) * N + n0 + bn + 4];
        __syncthreads();
#pragma unroll 4
        for (int k = 0; k < 16; ++k) {
            float a[8], b[8];
            *(float4*)&a[0] = *(const float4*)&As[k][ty * 8];
            *(float4*)&a[4] = *(const float4*)&As[k][ty * 8 + 4];
            *(float4*)&b[0] = *(const float4*)&Bs[k][tx * 8];
            *(float4*)&b[4] = *(const float4*)&Bs[k][tx * 8 + 4];
#pragma unroll
            for (int i = 0; i < 8; ++i)
#pragma unroll
                for (int j = 0; j < 8; ++j)
                    acc[i][j] = fmaf(a[i], b[j], acc[i][j]);
        }
        __syncthreads();
    }

#pragma unroll
    for (int i = 0; i < 8; ++i) {
        int o = o0 + ty * 8 + i;
        float sv = scale ? scale[o] : 1.0f;
        float bv = biasp[o];
        float r[8];
#pragma unroll
        for (int j = 0; j < 8; ++j)
            r[j] = fmaxf(fmaf(acc[i][j], sv, bv), 0.f);
        *(float4*)&Cp[(long)o * N + n0 + tx * 8]     = *(float4*)&r[0];
        *(float4*)&Cp[(long)o * N + n0 + tx * 8 + 4] = *(float4*)&r[4];
    }
}

// =====================================================================
// GEMM B: 64(O) x 256(N) tile, 256 threads, 8x8 micro-tile, Ktile 16.
// flags bit0: kmax; bit1: relu. add: per-point pre-scale addend.
// =====================================================================
__global__ void __launch_bounds__(256) gemmB(
    const float* __restrict__ A, const float* __restrict__ B, float* __restrict__ C,
    const float* __restrict__ scale, const float* __restrict__ bias,
    int K, int N, long sB, long sC, int flags,
    const float* __restrict__ add, long sAdd)
{
    __shared__ float As[16][64];
    __shared__ float Bs[16][256];
    const float* Bp = B + (long)blockIdx.z * sB;
    float* Cp = C + (long)blockIdx.z * sC;
    const int n0 = blockIdx.x * 256;
    const int tid = threadIdx.x;
    const int tx = tid & 31, ty = tid >> 5;

    const int ar = tid >> 2;
    const int aq = (tid & 3) * 4;
    const int bk = tid >> 4;
    const int bn = (tid & 15) * 16;

    float acc[8][8];
#pragma unroll
    for (int i = 0; i < 8; ++i)
#pragma unroll
        for (int j = 0; j < 8; ++j) acc[i][j] = 0.f;

    for (int k0 = 0; k0 < K; k0 += 16) {
        float4 a0 = *(const float4*)&A[(long)ar * K + k0 + aq];
        As[aq + 0][ar] = a0.x; As[aq + 1][ar] = a0.y;
        As[aq + 2][ar] = a0.z; As[aq + 3][ar] = a0.w;
#pragma unroll
        for (int q = 0; q < 4; ++q)
            *(float4*)&Bs[bk][bn + q * 4] =
                *(const float4*)&Bp[(long)(k0 + bk) * N + n0 + bn + q * 4];
        __syncthreads();
#pragma unroll 4
        for (int k = 0; k < 16; ++k) {
            float a[8], b[8];
            *(float4*)&a[0] = *(const float4*)&As[k][ty * 8];
            *(float4*)&a[4] = *(const float4*)&As[k][ty * 8 + 4];
            *(float4*)&b[0] = *(const float4*)&Bs[k][tx * 8];
            *(float4*)&b[4] = *(const float4*)&Bs[k][tx * 8 + 4];
#pragma unroll
            for (int i = 0; i < 8; ++i)
#pragma unroll
                for (int j = 0; j < 8; ++j)
                    acc[i][j] = fmaf(a[i], b[j], acc[i][j]);
        }
        __syncthreads();
    }

    const bool kmax = (flags & 1) != 0;
    const bool relu = (flags & 2) != 0;
#pragma unroll
    for (int i = 0; i < 8; ++i) {
        int o = ty * 8 + i;
        float sv = scale ? scale[o] : 1.0f;
        float bv = bias ? bias[o] : 0.0f;
        float t0 = 0.f, t1 = 0.f;
        if (add) {
            const float* ap = add + (long)blockIdx.z * sAdd + (long)o * 2048
                              + (n0 >> 2) + tx * 2;
            t0 = ap[0]; t1 = ap[1];
        }
        float r[8];
#pragma unroll
        for (int j = 0; j < 8; ++j) {
            float v = fmaf(acc[i][j] + ((j < 4) ? t0 : t1), sv, bv);
            r[j] = relu ? fmaxf(v, 0.f) : v;
        }
        if (kmax) {
            int p = (n0 >> 2) + tx * 2;
            Cp[(long)o * 2048 + p]     = fmaxf(fmaxf(r[0], r[1]), fmaxf(r[2], r[3]));
            Cp[(long)o * 2048 + p + 1] = fmaxf(fmaxf(r[4], r[5]), fmaxf(r[6], r[7]));
        } else {
            *(float4*)&Cp[(long)o * N + n0 + tx * 8]     = *(float4*)&r[0];
            *(float4*)&Cp[(long)o * N + n0 + tx * 8 + 4] = *(float4*)&r[4];
        }
    }
}

// ---------------- xx[b,n] = sum_c h2^2 ----------------
__global__ void xx_kernel()
{
    int t = blockIdx.x * blockDim.x + threadIdx.x;   // 8*2048
    int b = t >> 11, n = t & 2047;
    const float* h = d_h2 + (long)b * 64 * 2048;
    float acc = 0.f;
#pragma unroll
    for (int c = 0; c < 64; ++c) {
        float v = h[c * 2048 + n];
        acc = fmaf(v, v, acc);
    }
    d_xx[t] = acc;
}

// ---------------- build 3xTF32 split operands ----------------
__device__ __forceinline__ float tf32_rna(float x)
{
    uint32_t u;
    asm("cvt.rna.tf32.f32 %0, %1;" : "=r"(u) : "f"(x));
    return __uint_as_float(u);
}

__global__ void prep_pair()
{
    int t = blockIdx.x * blockDim.x + threadIdx.x;   // 8*2048
    int b = t >> 11, p = t & 2047;
    const float* h = d_h2 + (long)b * 64 * 2048;
    long base = (long)t * 72;
#pragma unroll 8
    for (int c = 0; c < 64; ++c) {
        float hv = h[c * 2048 + p];
        float a = 2.0f * hv;
        float ah = tf32_rna(a);
        float bh = tf32_rna(hv);
        d_pa_hi[base + c] = ah;
        d_pa_lo[base + c] = tf32_rna(a - ah);
        d_pb_hi[base + c] = bh;
        d_pb_lo[base + c] = tf32_rna(hv - bh);
    }
    float xv = d_xx[t];
    float xh = tf32_rna(xv);
    d_pa_hi[base + 64] = -1.0f;
    d_pa_lo[base + 64] = 0.0f;
    d_pb_hi[base + 64] = xh;
    d_pb_lo[base + 64] = tf32_rna(xv - xh);
#pragma unroll
    for (int c = 65; c < 72; ++c) {
        d_pa_hi[base + c] = 0.f; d_pa_lo[base + c] = 0.f;
        d_pb_hi[base + c] = 0.f; d_pb_lo[base + c] = 0.f;
    }
}

// ---------------- g1[b,c] = max_n h2[b,c,n] ----------------
__global__ void gmax_kernel()
{
    int bc = blockIdx.x;
    int tid = threadIdx.x;        // 256
    const float4* p = (const float4*)(d_h2 + (long)bc * 2048);
    float4 v0 = p[tid];
    float4 v1 = p[tid + 256];
    float m = fmaxf(fmaxf(fmaxf(v0.x, v0.y), fmaxf(v0.z, v0.w)),
                    fmaxf(fmaxf(v1.x, v1.y), fmaxf(v1.z, v1.w)));
    __shared__ float sm[256];
    sm[tid] = m;
    __syncthreads();
    for (int s = 128; s > 0; s >>= 1) {
        if (tid < s) sm[tid] = fmaxf(sm[tid], sm[tid + s]);
        __syncthreads();
    }
    if (tid == 0) d_g1[bc] = sm[0];
}

// ---------------- top-4 bubble inserts ----------------
// strict > : correct for ascending-m scan (ties keep earliest index)
__device__ __forceinline__ void ins4(float v, int m, float* V, int* I)
{
#pragma unroll
    for (int s = 0; s < 4; ++s) {
        if (v > V[s]) {
            float tv = V[s]; V[s] = v; v = tv;
            int   tm = I[s]; I[s] = m; m = tm;
        }
    }
}
// lexicographic (v desc, idx asc) : for merging unordered sublists
__device__ __forceinline__ void ins4t(float v, int m, float* V, int* I)
{
#pragma unroll
    for (int s = 0; s < 4; ++s) {
        bool better = (v > V[s]) || (v == V[s] && m < I[s]);
        if (better) {
            float tv = V[s]; V[s] = v; v = tv;
            int   tm = I[s]; I[s] = m; m = tm;
        }
    }
}

// =====================================================================
// pairwise top-4 via mma.sync tf32 (3xTF32).
// grid (16,8), block 256 (8 warps). Warp w owns n-rows n0+w*16..+15.
// s[n,m] = 2<h_n,h_m> - xx_m  (augmented K=72); rank-equivalent to pd.
// =====================================================================
__global__ void __launch_bounds__(256, 1) pairwise_mma()
{
    extern __shared__ float smB[];           // [2][128*76] hi, lo (77824 B)
    float* B_hi = smB;
    float* B_lo = smB + 128 * 76;

    const int tid = threadIdx.x;
    const int w = tid >> 5;
    const int lane = tid & 31;
    const int g = lane >> 2;                 // group 0..7
    const int t4 = lane & 3;                 // thread-in-group
    const int b = blockIdx.y;
    const int n0 = blockIdx.x * 128;

    // A fragments resident: rows row_lo = n0+w*16+g, row_hi = +8
    const long arow = (long)b * 2048 + n0 + w * 16 + g;
    const uint32_t* pah = (const uint32_t*)d_pa_hi + arow * 72;
    const uint32_t* pal = (const uint32_t*)d_pa_lo + arow * 72;
    uint32_t ah[9][4], al[9][4];
#pragma unroll
    for (int kc = 0; kc < 9; ++kc) {
        int k0 = kc * 8 + t4;
        ah[kc][0] = pah[k0];           ah[kc][1] = pah[8 * 72 + k0];
        ah[kc][2] = pah[k0 + 4];       ah[kc][3] = pah[8 * 72 + k0 + 4];
        al[kc][0] = pal[k0];           al[kc][1] = pal[8 * 72 + k0];
        al[kc][2] = pal[k0 + 4];       al[kc][3] = pal[8 * 72 + k0 + 4];
    }

    float Vlo[4] = {-1e30f, -1e30f, -1e30f, -1e30f};
    float Vhi[4] = {-1e30f, -1e30f, -1e30f, -1e30f};
    int   Ilo[4] = {0, 0, 0, 0};
    int   Ihi[4] = {0, 0, 0, 0};

    for (int tile = 0; tile < 16; ++tile) {
        __syncthreads();
        // stage B m-tile (128 m x 72 k, hi+lo), smem row stride 76
        {
            const long goff0 = ((long)b * 2048 + tile * 128) * 72;
            for (int idx = tid; idx < 128 * 18; idx += 256) {
                int row = idx / 18;
                int c4 = (idx - row * 18) * 4;
                long go = goff0 + (long)row * 72 + c4;
                *(float4*)&B_hi[row * 76 + c4] = *(const float4*)&d_pb_hi[go];
                *(float4*)&B_lo[row * 76 + c4] = *(const float4*)&d_pb_lo[go];
            }
        }
        __syncthreads();

#pragma unroll 1
        for (int sub = 0; sub < 16; ++sub) {
            float c0 = 0.f, c1 = 0.f, c2 = 0.f, c3 = 0.f;
            const uint32_t* Bh = (const uint32_t*)B_hi + (sub * 8 + g) * 76 + t4;
            const uint32_t* Bl = (const uint32_t*)B_lo + (sub * 8 + g) * 76 + t4;
#pragma unroll
            for (int kc = 0; kc < 9; ++kc) {
                uint32_t bh0 = Bh[kc * 8], bh1 = Bh[kc * 8 + 4];
                uint32_t bl0 = Bl[kc * 8], bl1 = Bl[kc * 8 + 4];
                asm volatile(
                    "mma.sync.aligned.m16n8k8.row.col.f32.tf32.tf32.f32 "
                    "{%0,%1,%2,%3}, {%4,%5,%6,%7}, {%8,%9}, {%0,%1,%2,%3};"
                    : "+f"(c0), "+f"(c1), "+f"(c2), "+f"(c3)
                    : "r"(ah[kc][0]), "r"(ah[kc][1]), "r"(ah[kc][2]), "r"(ah[kc][3]),
                      "r"(bh0), "r"(bh1));
                asm volatile(
                    "mma.sync.aligned.m16n8k8.row.col.f32.tf32.tf32.f32 "
                    "{%0,%1,%2,%3}, {%4,%5,%6,%7}, {%8,%9}, {%0,%1,%2,%3};"
                    : "+f"(c0), "+f"(c1), "+f"(c2), "+f"(c3)
                    : "r"(ah[kc][0]), "r"(ah[kc][1]), "r"(ah[kc][2]), "r"(ah[kc][3]),
                      "r"(bl0), "r"(bl1));
                if (kc < 8) {   // a_lo of pad/aug chunk is all zero
                    asm volatile(
                        "mma.sync.aligned.m16n8k8.row.col.f32.tf32.tf32.f32 "
                        "{%0,%1,%2,%3}, {%4,%5,%6,%7}, {%8,%9}, {%0,%1,%2,%3};"
                        : "+f"(c0), "+f"(c1), "+f"(c2), "+f"(c3)
                        : "r"(al[kc][0]), "r"(al[kc][1]), "r"(al[kc][2]), "r"(al[kc][3]),
                          "r"(bh0), "r"(bh1));
                }
            }
            // scan: c0/c1 -> row_lo at m = mg, mg+1; c2/c3 -> row_hi
            int mg = tile * 128 + sub * 8 + 2 * t4;
            if (fmaxf(c0, c1) > Vlo[3]) {
                ins4(c0, mg, Vlo, Ilo);
                ins4(c1, mg + 1, Vlo, Ilo);
            }
            if (fmaxf(c2, c3) > Vhi[3]) {
                ins4(c2, mg, Vhi, Ihi);
                ins4(c3, mg + 1, Vhi, Ihi);
            }
        }
    }

    // merge: reuse smem. entry e = (row_local*4 + t4); row_local in 0..127
    __syncthreads();
    float* mv = smB;                  // [128*4][4]
    int*   mi = (int*)(smB + 2048);   // [128*4][4]
    {
        int rlo = w * 16 + g, rhi = rlo + 8;
#pragma unroll
        for (int s = 0; s < 4; ++s) {
            mv[(rlo * 4 + t4) * 4 + s] = Vlo[s];
            mi[(rlo * 4 + t4) * 4 + s] = Ilo[s];
            mv[(rhi * 4 + t4) * 4 + s] = Vhi[s];
            mi[(rhi * 4 + t4) * 4 + s] = Ihi[s];
        }
    }
    __syncthreads();
    if (tid < 128) {
        float V[4] = {-1e30f, -1e30f, -1e30f, -1e30f};
        int   I[4] = {0, 0, 0, 0};
#pragma unroll
        for (int q = 0; q < 4; ++q)
#pragma unroll
            for (int s = 0; s < 4; ++s)
                ins4t(mv[(tid * 4 + q) * 4 + s], mi[(tid * 4 + q) * 4 + s], V, I);
        int baseo = (b * 2048 + n0 + tid) * 4;
        d_idx[baseo + 0] = I[0];
        d_idx[baseo + 1] = I[1];
        d_idx[baseo + 2] = I[2];
        d_idx[baseo + 3] = I[3];
    }
}

// ---------------- build gathered-nb features ----------------
__global__ void build_feat()
{
    long t = (long)blockIdx.x * blockDim.x + threadIdx.x;   // 8*64*8192
    int k = (int)(t & 3);
    int n = (int)((t >> 2) & 2047);
    int c = (int)((t >> 13) & 63);
    int b = (int)(t >> 19);
    const float* h = d_h2 + (long)b * 64 * 2048;
    int j = d_idx[((long)b * 2048 + n) * 4 + k];
    d_feat[t] = h[c * 2048 + j];
}

// ---------------- global-feature MLP: 64 -> 128 -> 128 ----------------
__global__ void gpath(const float* __restrict__ W3a, const float* __restrict__ s3a,
                      const float* __restrict__ b3a, const float* __restrict__ W3b,
                      const float* __restrict__ s3b, const float* __restrict__ b3b)
{
    __shared__ float gin[64];
    __shared__ float gmid[128];
    int b = blockIdx.x, tid = threadIdx.x;
    if (tid < 64) gin[tid] = d_g1[b * 64 + tid];
    __syncthreads();
    float acc = 0.f;
#pragma unroll
    for (int c = 0; c < 64; ++c) acc = fmaf(W3a[tid * 64 + c], gin[c], acc);
    gmid[tid] = fmaxf(fmaf(acc, s3a[tid], b3a[tid]), 0.f);
    __syncthreads();
    acc = 0.f;
#pragma unroll
    for (int c = 0; c < 128; ++c) acc = fmaf(W3b[tid * 128 + c], gmid[c], acc);
    d_g2[b * 128 + tid] = fmaxf(fmaf(acc, s3b[tid], b3b[tid]), 0.f);
}

// ---------------- gb[b][o] = bias4a[o] + W4a[o,64:192] . g2[b,:] ----------------
__global__ void gbias(const float* __restrict__ W4a, const float* __restrict__ bias4a)
{
    int b = blockIdx.x;
    int o = threadIdx.x;
    float acc = bias4a[o];
#pragma unroll
    for (int c = 0; c < 128; ++c)
        acc = fmaf(W4a[o * 192 + 64 + c], d_g2[b * 128 + c], acc);
    d_gb[b * 256 + o] = acc;
}

// ---------------- head: out[b,o,n] = W4b[o,:] @ h4[b,:,n] + bias ----------------
__global__ void out_kernel(const float* __restrict__ W4b,
                           const float* __restrict__ bias4b,
                           float* __restrict__ out)
{
    int t = blockIdx.x * blockDim.x + threadIdx.x;  // 8*2048
    int b = t >> 11, n = t & 2047;
    const float* h = d_h4 + (long)b * 256 * 2048;
    float a0 = bias4b[0], a1 = bias4b[1], a2 = bias4b[2];
#pragma unroll 4
    for (int c = 0; c < 256; ++c) {
        float hv = h[c * 2048 + n];
        a0 = fmaf(W4b[c], hv, a0);
        a1 = fmaf(W4b[256 + c], hv, a1);
        a2 = fmaf(W4b[512 + c], hv, a2);
    }
    out[((long)b * 3 + 0) * 2048 + n] = a0;
    out[((long)b * 3 + 1) * 2048 + n] = a1;
    out[((long)b * 3 + 2) * 2048 + n] = a2;
}

// ---------------- host launcher ----------------
extern "C" void kernel_launch(void* const* d_in, const int* in_sizes, int n_in,
                              void* d_out, int out_size)
{
    const float* x      = (const float*)d_in[0];
    const float* W_dup  = (const float*)d_in[1];
    const float* s_dup  = (const float*)d_in[2];
    const float* b_dup  = (const float*)d_in[3];
    const float* W_c1   = (const float*)d_in[4];
    const float* s_c1   = (const float*)d_in[5];
    const float* b_c1   = (const float*)d_in[6];
    const float* W2a    = (const float*)d_in[7];
    const float* s2a    = (const float*)d_in[8];
    const float* b2a    = (const float*)d_in[9];
    const float* W2b    = (const float*)d_in[10];
    const float* s2b    = (const float*)d_in[11];
    const float* b2b    = (const float*)d_in[12];
    const float* W2c    = (const float*)d_in[13];
    const float* s2c    = (const float*)d_in[14];
    const float* b2c    = (const float*)d_in[15];
    const float* W3a    = (const float*)d_in[16];
    const float* s3a    = (const float*)d_in[17];
    const float* b3a    = (const float*)d_in[18];
    const float* W3b    = (const float*)d_in[19];
    const float* s3b    = (const float*)d_in[20];
    const float* b3b    = (const float*)d_in[21];
    const float* W4a    = (const float*)d_in[22];
    const float* bias4a = (const float*)d_in[23];
    const float* W4b    = (const float*)d_in[24];
    const float* bias4b = (const float*)d_in[25];

    float *p_h1, *p_h2, *p_feat, *p_fa, *p_fb, *p_local, *p_h4;
    float *p_T, *p_gb, *p_W4a_c, *p_W2a_nb, *p_W2a_diff;
    cudaGetSymbolAddress((void**)&p_h1, d_h1);
    cudaGetSymbolAddress((void**)&p_h2, d_h2);
    cudaGetSymbolAddress((void**)&p_feat, d_feat);
    cudaGetSymbolAddress((void**)&p_fa, d_fa);
    cudaGetSymbolAddress((void**)&p_fb, d_fb);
    cudaGetSymbolAddress((void**)&p_local, d_local);
    cudaGetSymbolAddress((void**)&p_h4, d_h4);
    cudaGetSymbolAddress((void**)&p_T, d_T);
    cudaGetSymbolAddress((void**)&p_gb, d_gb);
    cudaGetSymbolAddress((void**)&p_W4a_c, d_W4a_c);
    cudaGetSymbolAddress((void**)&p_W2a_nb, d_W2a_nb);
    cudaGetSymbolAddress((void**)&p_W2a_diff, d_W2a_diff);

    static int smem_set = 0;
    if (!smem_set) {
        cudaFuncSetAttribute(pairwise_mma,
                             cudaFuncAttributeMaxDynamicSharedMemorySize, 77824);
        smem_set = 1;
    }

    prep_weights<<<80, 256>>>(W4a, W2a);

    // L1: (256x128) @ x[b](128x1024) -> h1
    gemmA<<<dim3(8, 2, 8), 256>>>(W_dup, x, p_h1, s_dup, b_dup,
                                  128, 1024, 131072L, 262144L, 0L);
    // L2: (64x128) @ h1[b] as (128x2048) -> h2
    gemmB<<<dim3(8, 1, 8), 256>>>(W_c1, p_h1, p_h2, s_c1, b_c1,
                                  128, 2048, 262144L, 131072L, 2, nullptr, 0L);
    xx_kernel<<<64, 256>>>();
    prep_pair<<<64, 256>>>();
    gmax_kernel<<<512, 256>>>();
    pairwise_mma<<<dim3(16, 8), 256, 77824>>>();
    build_feat<<<16384, 256>>>();
    // T[b,o,n] = (W2a_diff) @ h2
    gemmB<<<dim3(8, 1, 8), 256>>>(p_W2a_diff, p_h2, p_T, nullptr, nullptr,
                                  64, 2048, 131072L, 131072L, 0, nullptr, 0L);
    // conv2a: (64x64) @ feat(nb) + T broadcast -> fa
    gemmB<<<dim3(32, 1, 8), 256>>>(p_W2a_nb, p_feat, p_fa, s2a, b2a,
                                   64, 8192, 524288L, 524288L, 2, p_T, 131072L);
    // conv2b
    gemmB<<<dim3(32, 1, 8), 256>>>(W2b, p_fa, p_fb, s2b, b2b,
                                   64, 8192, 524288L, 524288L, 2, nullptr, 0L);
    // conv2c (fused max over k)
    gemmB<<<dim3(32, 1, 8), 256>>>(W2c, p_fb, p_local, s2c, b2c,
                                   64, 8192, 524288L, 131072L, 3, nullptr, 0L);
    gpath<<<8, 128>>>(W3a, s3a, b3a, W3b, s3b, b3b);
    gbias<<<8, 256>>>(W4a, bias4a);
    // head hidden: (256x64) @ local, folded per-batch bias
    gemmA<<<dim3(16, 2, 8), 256>>>(p_W4a_c, p_local, p_h4, nullptr, p_gb,
                                   64, 2048, 131072L, 524288L, 256L);
    out_kernel<<<64, 256>>>(W4b, bias4b, (float*)d_out);
}

// round 8
// speedup vs baseline: 1.0522x; 1.0522x over previous
#include <cuda_runtime.h>
#include <cstdint>

// ---------------- scratch (static device globals; no allocation) ----------------
__device__ float d_h1[8 * 256 * 1024];      // after dup conv  (8MB)
__device__ float d_h2[8 * 64 * 2048];       // after c1 conv   (4MB)
__device__ float d_xx[8 * 2048];            // per-point squared norms
__device__ float d_g1[8 * 64];              // global max feature
__device__ int   d_idx[8 * 2048 * 4];       // top-4 neighbor indices
__device__ float d_feat[8 * 64 * 8192];     // gathered nb features (16MB)
__device__ float d_fa[8 * 64 * 8192];       // ping              (16MB)
__device__ float d_fb[8 * 64 * 8192];       // pong              (16MB)
__device__ float d_local[8 * 64 * 2048];    // max over k        (4MB)
__device__ float d_T[8 * 64 * 2048];        // ctr-term for conv2a (4MB)
__device__ float d_gb[8 * 256];             // per-(b,o) folded head bias
__device__ float d_W4a_t[64 * 256];         // W4a[:,0:64] transposed [k][o]
__device__ float d_W2a_nb[64 * 64];         // W2a[:,0:64] compact
__device__ float d_W2a_diff[64 * 64];       // W2a[:,64:128]-W2a[:,0:64]
// symmetric-pairwise partial top-4: [b][rowblk][otherblk][row128][4]
__device__ float d_pv[8 * 16 * 16 * 128 * 4];   // 8MB
__device__ int   d_pi[8 * 16 * 16 * 128 * 4];   // 8MB

// ---------------- weight repack ----------------
__global__ void prep_weights(const float* __restrict__ W4a,
                             const float* __restrict__ W2a)
{
    int t = blockIdx.x * blockDim.x + threadIdx.x;
    if (t < 16384) {
        int k = t >> 8, o = t & 255;
        d_W4a_t[t] = W4a[o * 192 + k];          // transposed [k][o]
    } else if (t < 16384 + 4096) {
        int i = t - 16384;
        int o = i >> 6, c = i & 63;
        d_W2a_nb[i]   = W2a[o * 128 + c];
        d_W2a_diff[i] = W2a[o * 128 + 64 + c] - W2a[o * 128 + c];
    }
}

// =====================================================================
// GEMM A: 128(O) x 128(N) tile, 256 threads, 8x8 micro-tile, Ktile 16.
// =====================================================================
__global__ void __launch_bounds__(256) gemmA(
    const float* __restrict__ A, const float* __restrict__ B, float* __restrict__ C,
    const float* __restrict__ scale, const float* __restrict__ bias,
    int K, int N, long sB, long sC, long sBias)
{
    __shared__ float As[16][128];
    __shared__ float Bs[16][128];
    const float* Bp = B + (long)blockIdx.z * sB;
    float* Cp = C + (long)blockIdx.z * sC;
    const float* biasp = bias + (long)blockIdx.z * sBias;
    const int o0 = blockIdx.y * 128;
    const int n0 = blockIdx.x * 128;
    const int tid = threadIdx.x;
    const int tx = tid & 15, ty = tid >> 4;

    const int ar = tid >> 1;
    const int aq = (tid & 1) * 8;
    const int bk = tid >> 4;
    const int bn = (tid & 15) * 8;

    float acc[8][8];
#pragma unroll
    for (int i = 0; i < 8; ++i)
#pragma unroll
        for (int j = 0; j < 8; ++j) acc[i][j] = 0.f;

    for (int k0 = 0; k0 < K; k0 += 16) {
        float4 a0 = *(const float4*)&A[(long)(o0 + ar) * K + k0 + aq];
        float4 a1 = *(const float4*)&A[(long)(o0 + ar) * K + k0 + aq + 4];
        As[aq + 0][ar] = a0.x; As[aq + 1][ar] = a0.y;
        As[aq + 2][ar] = a0.z; As[aq + 3][ar] = a0.w;
        As[aq + 4][ar] = a1.x; As[aq + 5][ar] = a1.y;
        As[aq + 6][ar] = a1.z; As[aq + 7][ar] = a1.w;
        *(float4*)&Bs[bk][bn]     = *(const float4*)&Bp[(long)(k0 + bk) * N + n0 + bn];
        *(float4*)&Bs[bk][bn + 4] = *(const float4*)&Bp[(long)(k0 + bk) * N + n0 + bn + 4];
        __syncthreads();
#pragma unroll 4
        for (int k = 0; k < 16; ++k) {
            float a[8], b[8];
            *(float4*)&a[0] = *(const float4*)&As[k][ty * 8];
            *(float4*)&a[4] = *(const float4*)&As[k][ty * 8 + 4];
            *(float4*)&b[0] = *(const float4*)&Bs[k][tx * 8];
            *(float4*)&b[4] = *(const float4*)&Bs[k][tx * 8 + 4];
#pragma unroll
            for (int i = 0; i < 8; ++i)
#pragma unroll
                for (int j = 0; j < 8; ++j)
                    acc[i][j] = fmaf(a[i], b[j], acc[i][j]);
        }
        __syncthreads();
    }

#pragma unroll
    for (int i = 0; i < 8; ++i) {
        int o = o0 + ty * 8 + i;
        float sv = scale ? scale[o] : 1.0f;
        float bv = biasp[o];
        float r[8];
#pragma unroll
        for (int j = 0; j < 8; ++j)
            r[j] = fmaxf(fmaf(acc[i][j], sv, bv), 0.f);
        *(float4*)&Cp[(long)o * N + n0 + tx * 8]     = *(float4*)&r[0];
        *(float4*)&Cp[(long)o * N + n0 + tx * 8 + 4] = *(float4*)&r[4];
    }
}

// =====================================================================
// GEMM B: 64(O) x 256(N) tile, 256 threads, 8x8 micro-tile, Ktile 16.
// flags bit0: kmax; bit1: relu. add: per-point pre-scale addend.
// =====================================================================
__global__ void __launch_bounds__(256) gemmB(
    const float* __restrict__ A, const float* __restrict__ B, float* __restrict__ C,
    const float* __restrict__ scale, const float* __restrict__ bias,
    int K, int N, long sB, long sC, int flags,
    const float* __restrict__ add, long sAdd)
{
    __shared__ float As[16][64];
    __shared__ float Bs[16][256];
    const float* Bp = B + (long)blockIdx.z * sB;
    float* Cp = C + (long)blockIdx.z * sC;
    const int n0 = blockIdx.x * 256;
    const int tid = threadIdx.x;
    const int tx = tid & 31, ty = tid >> 5;

    const int ar = tid >> 2;
    const int aq = (tid & 3) * 4;
    const int bk = tid >> 4;
    const int bn = (tid & 15) * 16;

    float acc[8][8];
#pragma unroll
    for (int i = 0; i < 8; ++i)
#pragma unroll
        for (int j = 0; j < 8; ++j) acc[i][j] = 0.f;

    for (int k0 = 0; k0 < K; k0 += 16) {
        float4 a0 = *(const float4*)&A[(long)ar * K + k0 + aq];
        As[aq + 0][ar] = a0.x; As[aq + 1][ar] = a0.y;
        As[aq + 2][ar] = a0.z; As[aq + 3][ar] = a0.w;
#pragma unroll
        for (int q = 0; q < 4; ++q)
            *(float4*)&Bs[bk][bn + q * 4] =
                *(const float4*)&Bp[(long)(k0 + bk) * N + n0 + bn + q * 4];
        __syncthreads();
#pragma unroll 4
        for (int k = 0; k < 16; ++k) {
            float a[8], b[8];
            *(float4*)&a[0] = *(const float4*)&As[k][ty * 8];
            *(float4*)&a[4] = *(const float4*)&As[k][ty * 8 + 4];
            *(float4*)&b[0] = *(const float4*)&Bs[k][tx * 8];
            *(float4*)&b[4] = *(const float4*)&Bs[k][tx * 8 + 4];
#pragma unroll
            for (int i = 0; i < 8; ++i)
#pragma unroll
                for (int j = 0; j < 8; ++j)
                    acc[i][j] = fmaf(a[i], b[j], acc[i][j]);
        }
        __syncthreads();
    }

    const bool kmax = (flags & 1) != 0;
    const bool relu = (flags & 2) != 0;
#pragma unroll
    for (int i = 0; i < 8; ++i) {
        int o = ty * 8 + i;
        float sv = scale ? scale[o] : 1.0f;
        float bv = bias ? bias[o] : 0.0f;
        float t0 = 0.f, t1 = 0.f;
        if (add) {
            const float* ap = add + (long)blockIdx.z * sAdd + (long)o * 2048
                              + (n0 >> 2) + tx * 2;
            t0 = ap[0]; t1 = ap[1];
        }
        float r[8];
#pragma unroll
        for (int j = 0; j < 8; ++j) {
            float v = fmaf(acc[i][j] + ((j < 4) ? t0 : t1), sv, bv);
            r[j] = relu ? fmaxf(v, 0.f) : v;
        }
        if (kmax) {
            int p = (n0 >> 2) + tx * 2;
            Cp[(long)o * 2048 + p]     = fmaxf(fmaxf(r[0], r[1]), fmaxf(r[2], r[3]));
            Cp[(long)o * 2048 + p + 1] = fmaxf(fmaxf(r[4], r[5]), fmaxf(r[6], r[7]));
        } else {
            *(float4*)&Cp[(long)o * N + n0 + tx * 8]     = *(float4*)&r[0];
            *(float4*)&Cp[(long)o * N + n0 + tx * 8 + 4] = *(float4*)&r[4];
        }
    }
}

// ---------------- xx[b,n] = sum_c h2^2 (same chain as dot) ----------------
__global__ void xx_kernel()
{
    int t = blockIdx.x * blockDim.x + threadIdx.x;   // 8*2048
    int b = t >> 11, n = t & 2047;
    const float* h = d_h2 + (long)b * 64 * 2048;
    float acc = 0.f;
#pragma unroll
    for (int c = 0; c < 64; ++c) {
        float v = h[c * 2048 + n];
        acc = fmaf(v, v, acc);
    }
    d_xx[t] = acc;
}

// ---------------- g1[b,c] = max_n h2[b,c,n] ----------------
__global__ void gmax_kernel()
{
    int bc = blockIdx.x;
    int tid = threadIdx.x;        // 256
    const float4* p = (const float4*)(d_h2 + (long)bc * 2048);
    float4 v0 = p[tid];
    float4 v1 = p[tid + 256];
    float m = fmaxf(fmaxf(fmaxf(v0.x, v0.y), fmaxf(v0.z, v0.w)),
                    fmaxf(fmaxf(v1.x, v1.y), fmaxf(v1.z, v1.w)));
    __shared__ float sm[256];
    sm[tid] = m;
    __syncthreads();
    for (int s = 128; s > 0; s >>= 1) {
        if (tid < s) sm[tid] = fmaxf(sm[tid], sm[tid + s]);
        __syncthreads();
    }
    if (tid == 0) d_g1[bc] = sm[0];
}

// ---------------- top-4 inserts ----------------
// strict > : for ascending-index scans (ties keep earliest index)
__device__ __forceinline__ void ins4(float v, int m, float* V, int* I)
{
#pragma unroll
    for (int s = 0; s < 4; ++s) {
        if (v > V[s]) {
            float tv = V[s]; V[s] = v; v = tv;
            int   tm = I[s]; I[s] = m; m = tm;
        }
    }
}
// lexicographic (value desc, index asc) : exact cross-list merge
__device__ __forceinline__ void ins4t(float v, int m, float* V, int* I)
{
#pragma unroll
    for (int s = 0; s < 4; ++s) {
        bool better = (v > V[s]) || (v == V[s] && m < I[s]);
        if (better) {
            float tv = V[s]; V[s] = v; v = tv;
            int   tm = I[s]; I[s] = m; m = tm;
        }
    }
}

// =====================================================================
// symmetric pairwise: grid (136, 8), block 256. Pair (I<=J) of 128-pt blocks.
// Computes dot tile once; scans rows (I-side) and cols (J-side) with
// s = 2*dot - xx_other (rank-equivalent to pd; xn const per query row).
// Writes per-(row, otherblock) top-4 partials to gmem.
// =====================================================================
__global__ void __launch_bounds__(256) sym_pair()
{
    extern __shared__ float smem[];
    float* score = smem;                       // [128][129]  (66048 B)
    float* smI   = smem;                       // alias (dead before score writes)
    float* smJ   = smem + 128 * 129;           // [64][128]   (32768 B)
    float* sxxI  = smJ + 64 * 128;             // [128]
    float* sxxJ  = sxxI + 128;                 // [128]

    // decode pair index -> (I, J), I <= J
    int I = 0, J = 0;
    {
        int rem = blockIdx.x;
#pragma unroll
        for (int i = 0; i < 16; ++i) {
            int cnt = 16 - i;
            if (rem < cnt) { I = i; J = i + rem; break; }
            rem -= cnt;
        }
    }
    const int b = blockIdx.y;
    const int tid = threadIdx.x;
    const int nI = I * 128, nJ = J * 128;
    const float* h = d_h2 + (long)b * 64 * 2048;

    // stage I rows (into score region), J cols, xx
    for (int idx = tid; idx < 2048; idx += 256) {
        int c = idx >> 5, q4 = (idx & 31) * 4;
        *(float4*)&smI[c * 128 + q4] = *(const float4*)&h[c * 2048 + nI + q4];
        *(float4*)&smJ[c * 128 + q4] = *(const float4*)&h[c * 2048 + nJ + q4];
    }
    if (tid < 128) {
        sxxI[tid] = d_xx[b * 2048 + nI + tid];
        sxxJ[tid] = d_xx[b * 2048 + nJ + tid];
    }
    __syncthreads();

    // each thread owns I-row r, m-half mh; pull hn to registers
    const int r = tid >> 1;
    const int mh = (tid & 1) << 6;   // 0 or 64
    float hn[64];
#pragma unroll
    for (int c = 0; c < 64; ++c) hn[c] = smI[c * 128 + r];
    __syncthreads();                 // smI dead; score may now overwrite

    // compute dot(r, mh..mh+63) and write to score (chain identical to R5)
#pragma unroll 1
    for (int mm = 0; mm < 64; mm += 8) {
        float dot[8];
#pragma unroll
        for (int j = 0; j < 8; ++j) dot[j] = 0.f;
#pragma unroll
        for (int c = 0; c < 64; ++c) {
            float4 s0 = *(const float4*)&smJ[c * 128 + mh + mm];
            float4 s1 = *(const float4*)&smJ[c * 128 + mh + mm + 4];
            float hv = hn[c];
            dot[0] = fmaf(hv, s0.x, dot[0]);
            dot[1] = fmaf(hv, s0.y, dot[1]);
            dot[2] = fmaf(hv, s0.z, dot[2]);
            dot[3] = fmaf(hv, s0.w, dot[3]);
            dot[4] = fmaf(hv, s1.x, dot[4]);
            dot[5] = fmaf(hv, s1.y, dot[5]);
            dot[6] = fmaf(hv, s1.z, dot[6]);
            dot[7] = fmaf(hv, s1.w, dot[7]);
        }
#pragma unroll
        for (int j = 0; j < 8; ++j)
            score[r * 129 + mh + mm + j] = dot[j];
    }
    __syncthreads();

    if (tid < 128) {
        // I-side: query nI+tid scans m ascending (neighbors nJ+m)
        float V[4] = {-1e30f, -1e30f, -1e30f, -1e30f};
        int   Ix[4] = {0, 0, 0, 0};
        const float* srow = &score[tid * 129];
#pragma unroll 4
        for (int m = 0; m < 128; ++m) {
            float s = fmaf(2.0f, srow[m], -sxxJ[m]);
            if (s > V[3]) ins4(s, nJ + m, V, Ix);
        }
        long base = ((((long)b * 16 + I) * 16 + J) * 128 + tid) * 4;
        *(float4*)&d_pv[base] = make_float4(V[0], V[1], V[2], V[3]);
        *(int4*)&d_pi[base] = make_int4(Ix[0], Ix[1], Ix[2], Ix[3]);
    } else if (I < J) {
        // J-side: query nJ+m scans r ascending (neighbors nI+r)
        int m = tid - 128;
        float V[4] = {-1e30f, -1e30f, -1e30f, -1e30f};
        int   Ix[4] = {0, 0, 0, 0};
#pragma unroll 4
        for (int rr = 0; rr < 128; ++rr) {
            float s = fmaf(2.0f, score[rr * 129 + m], -sxxI[rr]);
            if (s > V[3]) ins4(s, nI + rr, V, Ix);
        }
        long base = ((((long)b * 16 + J) * 16 + I) * 128 + m) * 4;
        *(float4*)&d_pv[base] = make_float4(V[0], V[1], V[2], V[3]);
        *(int4*)&d_pi[base] = make_int4(Ix[0], Ix[1], Ix[2], Ix[3]);
    }
}

// ---------------- exact lexicographic merge of 16 partials per row ----------
__global__ void merge_topk()
{
    int row = blockIdx.x * 256 + threadIdx.x;   // 0..2047
    int b = blockIdx.y;
    int rb = row >> 7, rl = row & 127;
    long pbase = ((((long)b * 16 + rb) * 16) * 128 + rl) * 4;

    float V[4] = {-1e30f, -1e30f, -1e30f, -1e30f};
    int   I[4] = {0, 0, 0, 0};
#pragma unroll
    for (int o = 0; o < 16; ++o) {
        float4 v = *(const float4*)&d_pv[pbase + (long)o * 512];
        int4  ix = *(const int4*)&d_pi[pbase + (long)o * 512];
        ins4t(v.x, ix.x, V, I);
        ins4t(v.y, ix.y, V, I);
        ins4t(v.z, ix.z, V, I);
        ins4t(v.w, ix.w, V, I);
    }
    int baseo = (b * 2048 + row) * 4;
    d_idx[baseo + 0] = I[0];
    d_idx[baseo + 1] = I[1];
    d_idx[baseo + 2] = I[2];
    d_idx[baseo + 3] = I[3];
}

// ---------------- build gathered-nb features ----------------
__global__ void build_feat()
{
    long t = (long)blockIdx.x * blockDim.x + threadIdx.x;   // 8*64*8192
    int k = (int)(t & 3);
    int n = (int)((t >> 2) & 2047);
    int c = (int)((t >> 13) & 63);
    int b = (int)(t >> 19);
    const float* h = d_h2 + (long)b * 64 * 2048;
    int j = d_idx[((long)b * 2048 + n) * 4 + k];
    d_feat[t] = h[c * 2048 + j];
}

// ---------------- fused g-path MLP + head-bias fold ----------------
__global__ void gpath_gbias(
    const float* __restrict__ W3a, const float* __restrict__ s3a,
    const float* __restrict__ b3a, const float* __restrict__ W3b,
    const float* __restrict__ s3b, const float* __restrict__ b3b,
    const float* __restrict__ W4a, const float* __restrict__ bias4a)
{
    __shared__ float gin[64];
    __shared__ float gmid[128];
    __shared__ float g2s[128];
    int b = blockIdx.x, tid = threadIdx.x;
    if (tid < 64) gin[tid] = d_g1[b * 64 + tid];
    __syncthreads();
    if (tid < 128) {
        float acc = 0.f;
#pragma unroll
        for (int c = 0; c < 64; ++c) acc = fmaf(W3a[tid * 64 + c], gin[c], acc);
        gmid[tid] = fmaxf(fmaf(acc, s3a[tid], b3a[tid]), 0.f);
    }
    __syncthreads();
    if (tid < 128) {
        float acc = 0.f;
#pragma unroll
        for (int c = 0; c < 128; ++c) acc = fmaf(W3b[tid * 128 + c], gmid[c], acc);
        g2s[tid] = fmaxf(fmaf(acc, s3b[tid], b3b[tid]), 0.f);
    }
    __syncthreads();
    {
        int o = tid;   // 256
        float acc = bias4a[o];
#pragma unroll
        for (int c = 0; c < 128; ++c)
            acc = fmaf(W4a[o * 192 + 64 + c], g2s[c], acc);
        d_gb[b * 256 + o] = acc;
    }
}

// =====================================================================
// fused head: h4 = relu(W4a_c @ local + gb); out = W4b @ h4 + bias4b.
// grid (16, 8), block 256. Two o-passes of 128; deterministic reduction.
// =====================================================================
__global__ void __launch_bounds__(256) head_out(
    const float* __restrict__ W4b, const float* __restrict__ bias4b,
    float* __restrict__ out)
{
    extern __shared__ float smem[];
    float* As  = smem;                 // [64][256]   65536 B (k-major, pre-transposed)
    float* Bs  = As + 64 * 256;        // [64][128]   32768 B
    float* po  = Bs + 64 * 128;        // [16][3][128] 24576 B
    float* sgb = po + 16 * 3 * 128;    // [256]
    float* sw  = sgb + 256;            // [3][256]

    const int b = blockIdx.y;
    const int n0 = blockIdx.x * 128;
    const int tid = threadIdx.x;
    const int tx = tid & 15, ty = tid >> 4;
    const float* loc = d_local + (long)b * 64 * 2048;

    // stage
    for (int idx = tid; idx < 16384; idx += 256)
        As[idx] = d_W4a_t[idx];                       // already [k][o]
    for (int idx = tid; idx < 2048; idx += 256) {
        int k = idx >> 5, q4 = (idx & 31) * 4;
        *(float4*)&Bs[k * 128 + q4] = *(const float4*)&loc[k * 2048 + n0 + q4];
    }
    if (tid < 256) sgb[tid] = d_gb[b * 256 + tid];
    for (int idx = tid; idx < 768; idx += 256) sw[idx] = W4b[idx];
    __syncthreads();

    float p[3][8];
#pragma unroll
    for (int q = 0; q < 3; ++q)
#pragma unroll
        for (int j = 0; j < 8; ++j) p[q][j] = 0.f;

#pragma unroll
    for (int pass = 0; pass < 2; ++pass) {
        float acc[8][8];
#pragma unroll
        for (int i = 0; i < 8; ++i)
#pragma unroll
            for (int j = 0; j < 8; ++j) acc[i][j] = 0.f;
#pragma unroll 4
        for (int k = 0; k < 64; ++k) {
            float a[8], bb[8];
            *(float4*)&a[0] = *(const float4*)&As[k * 256 + pass * 128 + ty * 8];
            *(float4*)&a[4] = *(const float4*)&As[k * 256 + pass * 128 + ty * 8 + 4];
            *(float4*)&bb[0] = *(const float4*)&Bs[k * 128 + tx * 8];
            *(float4*)&bb[4] = *(const float4*)&Bs[k * 128 + tx * 8 + 4];
#pragma unroll
            for (int i = 0; i < 8; ++i)
#pragma unroll
                for (int j = 0; j < 8; ++j)
                    acc[i][j] = fmaf(a[i], bb[j], acc[i][j]);
        }
#pragma unroll
        for (int i = 0; i < 8; ++i) {
            int o = pass * 128 + ty * 8 + i;
            float g = sgb[o];
            float w0 = sw[o], w1 = sw[256 + o], w2 = sw[512 + o];
#pragma unroll
            for (int j = 0; j < 8; ++j) {
                float r = fmaxf(acc[i][j] + g, 0.f);
                p[0][j] = fmaf(w0, r, p[0][j]);
                p[1][j] = fmaf(w1, r, p[1][j]);
                p[2][j] = fmaf(w2, r, p[2][j]);
            }
        }
    }

    // publish partials: po[ty][q][n128]
#pragma unroll
    for (int q = 0; q < 3; ++q)
#pragma unroll
        for (int j = 0; j < 8; ++j)
            po[(ty * 3 + q) * 128 + tx * 8 + j] = p[q][j];
    __syncthreads();

    // deterministic fixed-order reduction over ty
    for (int item = tid; item < 384; item += 256) {
        int q = item >> 7, nn = item & 127;
        float s = bias4b[q];
#pragma unroll
        for (int t = 0; t < 16; ++t)
            s += po[(t * 3 + q) * 128 + nn];
        out[((long)b * 3 + q) * 2048 + n0 + nn] = s;
    }
}

// ---------------- host launcher ----------------
extern "C" void kernel_launch(void* const* d_in, const int* in_sizes, int n_in,
                              void* d_out, int out_size)
{
    const float* x      = (const float*)d_in[0];
    const float* W_dup  = (const float*)d_in[1];
    const float* s_dup  = (const float*)d_in[2];
    const float* b_dup  = (const float*)d_in[3];
    const float* W_c1   = (const float*)d_in[4];
    const float* s_c1   = (const float*)d_in[5];
    const float* b_c1   = (const float*)d_in[6];
    const float* W2a    = (const float*)d_in[7];
    const float* s2a    = (const float*)d_in[8];
    const float* b2a    = (const float*)d_in[9];
    const float* W2b    = (const float*)d_in[10];
    const float* s2b    = (const float*)d_in[11];
    const float* b2b    = (const float*)d_in[12];
    const float* W2c    = (const float*)d_in[13];
    const float* s2c    = (const float*)d_in[14];
    const float* b2c    = (const float*)d_in[15];
    const float* W3a    = (const float*)d_in[16];
    const float* s3a    = (const float*)d_in[17];
    const float* b3a    = (const float*)d_in[18];
    const float* W3b    = (const float*)d_in[19];
    const float* s3b    = (const float*)d_in[20];
    const float* b3b    = (const float*)d_in[21];
    const float* W4a    = (const float*)d_in[22];
    const float* bias4a = (const float*)d_in[23];
    const float* W4b    = (const float*)d_in[24];
    const float* bias4b = (const float*)d_in[25];

    float *p_h1, *p_h2, *p_feat, *p_fa, *p_fb, *p_local;
    float *p_T, *p_W2a_nb, *p_W2a_diff;
    cudaGetSymbolAddress((void**)&p_h1, d_h1);
    cudaGetSymbolAddress((void**)&p_h2, d_h2);
    cudaGetSymbolAddress((void**)&p_feat, d_feat);
    cudaGetSymbolAddress((void**)&p_fa, d_fa);
    cudaGetSymbolAddress((void**)&p_fb, d_fb);
    cudaGetSymbolAddress((void**)&p_local, d_local);
    cudaGetSymbolAddress((void**)&p_T, d_T);
    cudaGetSymbolAddress((void**)&p_W2a_nb, d_W2a_nb);
    cudaGetSymbolAddress((void**)&p_W2a_diff, d_W2a_diff);

    static int attr_set = 0;
    if (!attr_set) {
        cudaFuncSetAttribute(sym_pair,
                             cudaFuncAttributeMaxDynamicSharedMemorySize, 99840);
        cudaFuncSetAttribute(head_out,
                             cudaFuncAttributeMaxDynamicSharedMemorySize, 128000);
        attr_set = 1;
    }

    prep_weights<<<80, 256>>>(W4a, W2a);

    // L1: (256x128) @ x[b](128x1024) -> h1
    gemmA<<<dim3(8, 2, 8), 256>>>(W_dup, x, p_h1, s_dup, b_dup,
                                  128, 1024, 131072L, 262144L, 0L);
    // L2: (64x128) @ h1[b] as (128x2048) -> h2
    gemmB<<<dim3(8, 1, 8), 256>>>(W_c1, p_h1, p_h2, s_c1, b_c1,
                                  128, 2048, 262144L, 131072L, 2, nullptr, 0L);
    xx_kernel<<<64, 256>>>();
    gmax_kernel<<<512, 256>>>();
    sym_pair<<<dim3(136, 8), 256, 99840>>>();
    merge_topk<<<dim3(8, 8), 256>>>();
    build_feat<<<16384, 256>>>();
    // T[b,o,n] = (W2a_diff) @ h2
    gemmB<<<dim3(8, 1, 8), 256>>>(p_W2a_diff, p_h2, p_T, nullptr, nullptr,
                                  64, 2048, 131072L, 131072L, 0, nullptr, 0L);
    // conv2a: (64x64) @ feat(nb) + T broadcast -> fa
    gemmB<<<dim3(32, 1, 8), 256>>>(p_W2a_nb, p_feat, p_fa, s2a, b2a,
                                   64, 8192, 524288L, 524288L, 2, p_T, 131072L);
    // conv2b
    gemmB<<<dim3(32, 1, 8), 256>>>(W2b, p_fa, p_fb, s2b, b2b,
                                   64, 8192, 524288L, 524288L, 2, nullptr, 0L);
    // conv2c (fused max over k)
    gemmB<<<dim3(32, 1, 8), 256>>>(W2c, p_fb, p_local, s2c, b2c,
                                   64, 8192, 524288L, 131072L, 3, nullptr, 0L);
    gpath_gbias<<<8, 256>>>(W3a, s3a, b3a, W3b, s3b, b3b, W4a, bias4a);
    // fused head + out
    head_out<<<dim3(16, 8), 256, 128000>>>(W4b, bias4b, (float*)d_out);
}

// round 9
// speedup vs baseline: 1.4830x; 1.4095x over previous
#include <cuda_runtime.h>
#include <cstdint>

// ---------------- scratch (static device globals; no allocation) ----------------
__device__ float d_h1[8 * 256 * 1024];      // after dup conv  (8MB)
__device__ float d_h2[8 * 64 * 2048];       // after c1 conv   (4MB)
__device__ float d_xx[8 * 2048];            // per-point squared norms
__device__ float d_g1[8 * 64];              // global max feature (int-atomic bits)
__device__ float d_local[8 * 64 * 2048];    // max over k        (4MB)
__device__ float d_W4a_t[64 * 256];         // W4a[:,0:64] transposed [k][o]
__device__ float d_W2a_nb_t[64 * 64];       // W2a[:,0:64]  as [c][o]
__device__ float d_W2a_diff_t[64 * 64];     // (W2a[:,64:128]-W2a[:,0:64]) as [c][o]
__device__ float d_W2b_t[64 * 64];          // W2b as [c][o]
__device__ float d_W2c_t[64 * 64];          // W2c as [c][o]
// symmetric-pairwise partial top-4: [b][rowblk][otherblk][row128][4]
__device__ float d_pv[8 * 16 * 16 * 128 * 4];   // 8MB
__device__ int   d_pi[8 * 16 * 16 * 128 * 4];   // 8MB

// ---------------- weight repack + g1 reset ----------------
__global__ void prep_weights(const float* __restrict__ W4a,
                             const float* __restrict__ W2a,
                             const float* __restrict__ W2b,
                             const float* __restrict__ W2c)
{
    int t = blockIdx.x * blockDim.x + threadIdx.x;
    if (t < 16384) {
        int k = t >> 8, o = t & 255;
        d_W4a_t[t] = W4a[o * 192 + k];
    } else if (t < 20480) {
        int i = t - 16384;
        int c = i >> 6, o = i & 63;
        float w0 = W2a[o * 128 + c];
        d_W2a_nb_t[i]   = w0;
        d_W2a_diff_t[i] = W2a[o * 128 + 64 + c] - w0;
    } else if (t < 24576) {
        int i = t - 20480;
        int c = i >> 6, o = i & 63;
        d_W2b_t[i] = W2b[o * 64 + c];
    } else if (t < 28672) {
        int i = t - 24576;
        int c = i >> 6, o = i & 63;
        d_W2c_t[i] = W2c[o * 64 + c];
    } else if (t < 29184) {
        d_g1[t - 28672] = 0.0f;
    }
}

// =====================================================================
// GEMM A: 128(O) x 128(N) tile, 256 threads, 8x8 micro-tile, Ktile 16.
// =====================================================================
__global__ void __launch_bounds__(256) gemmA(
    const float* __restrict__ A, const float* __restrict__ B, float* __restrict__ C,
    const float* __restrict__ scale, const float* __restrict__ bias,
    int K, int N, long sB, long sC)
{
    __shared__ float As[16][128];
    __shared__ float Bs[16][128];
    const float* Bp = B + (long)blockIdx.z * sB;
    float* Cp = C + (long)blockIdx.z * sC;
    const int o0 = blockIdx.y * 128;
    const int n0 = blockIdx.x * 128;
    const int tid = threadIdx.x;
    const int tx = tid & 15, ty = tid >> 4;

    const int ar = tid >> 1;
    const int aq = (tid & 1) * 8;
    const int bk = tid >> 4;
    const int bn = (tid & 15) * 8;

    float acc[8][8];
#pragma unroll
    for (int i = 0; i < 8; ++i)
#pragma unroll
        for (int j = 0; j < 8; ++j) acc[i][j] = 0.f;

    for (int k0 = 0; k0 < K; k0 += 16) {
        float4 a0 = *(const float4*)&A[(long)(o0 + ar) * K + k0 + aq];
        float4 a1 = *(const float4*)&A[(long)(o0 + ar) * K + k0 + aq + 4];
        As[aq + 0][ar] = a0.x; As[aq + 1][ar] = a0.y;
        As[aq + 2][ar] = a0.z; As[aq + 3][ar] = a0.w;
        As[aq + 4][ar] = a1.x; As[aq + 5][ar] = a1.y;
        As[aq + 6][ar] = a1.z; As[aq + 7][ar] = a1.w;
        *(float4*)&Bs[bk][bn]     = *(const float4*)&Bp[(long)(k0 + bk) * N + n0 + bn];
        *(float4*)&Bs[bk][bn + 4] = *(const float4*)&Bp[(long)(k0 + bk) * N + n0 + bn + 4];
        __syncthreads();
#pragma unroll 4
        for (int k = 0; k < 16; ++k) {
            float a[8], b[8];
            *(float4*)&a[0] = *(const float4*)&As[k][ty * 8];
            *(float4*)&a[4] = *(const float4*)&As[k][ty * 8 + 4];
            *(float4*)&b[0] = *(const float4*)&Bs[k][tx * 8];
            *(float4*)&b[4] = *(const float4*)&Bs[k][tx * 8 + 4];
#pragma unroll
            for (int i = 0; i < 8; ++i)
#pragma unroll
                for (int j = 0; j < 8; ++j)
                    acc[i][j] = fmaf(a[i], b[j], acc[i][j]);
        }
        __syncthreads();
    }

#pragma unroll
    for (int i = 0; i < 8; ++i) {
        int o = o0 + ty * 8 + i;
        float sv = scale[o];
        float bv = bias[o];
        float r[8];
#pragma unroll
        for (int j = 0; j < 8; ++j)
            r[j] = fmaxf(fmaf(acc[i][j], sv, bv), 0.f);
        *(float4*)&Cp[(long)o * N + n0 + tx * 8]     = *(float4*)&r[0];
        *(float4*)&Cp[(long)o * N + n0 + tx * 8 + 4] = *(float4*)&r[4];
    }
}

// =====================================================================
// GEMM L2: 64(O) x 256(N) tile + fused xx (col sumsq) + gmax stats.
// C = relu((A@B)*s + b). O must be 64 (full channel dim per block).
// =====================================================================
__global__ void __launch_bounds__(256) gemmL2(
    const float* __restrict__ A, const float* __restrict__ B, float* __restrict__ C,
    const float* __restrict__ scale, const float* __restrict__ bias,
    int K, int N, long sB, long sC)
{
    __shared__ float As[16][64];
    __shared__ float Bs[16][256];
    __shared__ float ps[8 * 256];      // xx partials [ty][col]
    __shared__ float pm[64 * 32];      // gmax partials [o][tx]
    const int b = blockIdx.z;
    const float* Bp = B + (long)b * sB;
    float* Cp = C + (long)b * sC;
    const int n0 = blockIdx.x * 256;
    const int tid = threadIdx.x;
    const int tx = tid & 31, ty = tid >> 5;

    const int ar = tid >> 2;
    const int aq = (tid & 3) * 4;
    const int bk = tid >> 4;
    const int bn = (tid & 15) * 16;

    float acc[8][8];
#pragma unroll
    for (int i = 0; i < 8; ++i)
#pragma unroll
        for (int j = 0; j < 8; ++j) acc[i][j] = 0.f;

    for (int k0 = 0; k0 < K; k0 += 16) {
        float4 a0 = *(const float4*)&A[(long)ar * K + k0 + aq];
        As[aq + 0][ar] = a0.x; As[aq + 1][ar] = a0.y;
        As[aq + 2][ar] = a0.z; As[aq + 3][ar] = a0.w;
#pragma unroll
        for (int q = 0; q < 4; ++q)
            *(float4*)&Bs[bk][bn + q * 4] =
                *(const float4*)&Bp[(long)(k0 + bk) * N + n0 + bn + q * 4];
        __syncthreads();
#pragma unroll 4
        for (int k = 0; k < 16; ++k) {
            float a[8], bb[8];
            *(float4*)&a[0] = *(const float4*)&As[k][ty * 8];
            *(float4*)&a[4] = *(const float4*)&As[k][ty * 8 + 4];
            *(float4*)&bb[0] = *(const float4*)&Bs[k][tx * 8];
            *(float4*)&bb[4] = *(const float4*)&Bs[k][tx * 8 + 4];
#pragma unroll
            for (int i = 0; i < 8; ++i)
#pragma unroll
                for (int j = 0; j < 8; ++j)
                    acc[i][j] = fmaf(a[i], bb[j], acc[i][j]);
        }
        __syncthreads();
    }

    float px[8];
#pragma unroll
    for (int j = 0; j < 8; ++j) px[j] = 0.f;

#pragma unroll
    for (int i = 0; i < 8; ++i) {
        int o = ty * 8 + i;
        float sv = scale[o];
        float bv = bias[o];
        float r[8];
        float gm = 0.f;
#pragma unroll
        for (int j = 0; j < 8; ++j) {
            r[j] = fmaxf(fmaf(acc[i][j], sv, bv), 0.f);
            px[j] = fmaf(r[j], r[j], px[j]);
            gm = fmaxf(gm, r[j]);
        }
        pm[o * 32 + tx] = gm;
        *(float4*)&Cp[(long)o * N + n0 + tx * 8]     = *(float4*)&r[0];
        *(float4*)&Cp[(long)o * N + n0 + tx * 8 + 4] = *(float4*)&r[4];
    }
#pragma unroll
    for (int j = 0; j < 8; ++j)
        ps[ty * 256 + tx * 8 + j] = px[j];
    __syncthreads();

    // xx: fixed ascending-ty reduction per column
    {
        float s = 0.f;
#pragma unroll
        for (int t = 0; t < 8; ++t) s += ps[t * 256 + tid];
        d_xx[b * 2048 + n0 + tid] = s;
    }
    // gmax: per-o max over 32 tx, then global int atomicMax (values >= 0)
    if (tid < 64) {
        float m = 0.f;
#pragma unroll
        for (int t = 0; t < 32; ++t) m = fmaxf(m, pm[tid * 32 + t]);
        atomicMax((int*)&d_g1[b * 64 + tid], __float_as_int(m));
    }
}

// ---------------- top-4 inserts ----------------
__device__ __forceinline__ void ins4(float v, int m, float* V, int* I)
{
#pragma unroll
    for (int s = 0; s < 4; ++s) {
        if (v > V[s]) {
            float tv = V[s]; V[s] = v; v = tv;
            int   tm = I[s]; I[s] = m; m = tm;
        }
    }
}
__device__ __forceinline__ void ins4t(float v, int m, float* V, int* I)
{
#pragma unroll
    for (int s = 0; s < 4; ++s) {
        bool better = (v > V[s]) || (v == V[s] && m < I[s]);
        if (better) {
            float tv = V[s]; V[s] = v; v = tv;
            int   tm = I[s]; I[s] = m; m = tm;
        }
    }
}

// =====================================================================
// symmetric pairwise, GEMM micro-tiled. grid (136, 8), block 256.
// Pair (I<=J): dot tile via 8x8 micro-tile (94% FFMA density),
// score smem aliases operand buffers; two scan phases as before.
// =====================================================================
__global__ void __launch_bounds__(256) sym_pair()
{
    extern __shared__ float sm[];
    float* smI   = sm;                 // [64][128] phase 1
    float* smJ   = sm + 8192;          // [64][128] phase 1
    float* score = sm;                 // [128][129] phase 2 (aliases operands)
    float* sxxI  = sm + 16512;         // [128]
    float* sxxJ  = sm + 16640;         // [128]

    int I = 0, J = 0;
    {
        int rem = blockIdx.x;
#pragma unroll
        for (int i = 0; i < 16; ++i) {
            int cnt = 16 - i;
            if (rem < cnt) { I = i; J = i + rem; break; }
            rem -= cnt;
        }
    }
    const int b = blockIdx.y;
    const int tid = threadIdx.x;
    const int nI = I * 128, nJ = J * 128;
    const float* h = d_h2 + (long)b * 64 * 2048;

    for (int idx = tid; idx < 2048; idx += 256) {
        int c = idx >> 5, q4 = (idx & 31) * 4;
        *(float4*)&smI[c * 128 + q4] = *(const float4*)&h[c * 2048 + nI + q4];
        *(float4*)&smJ[c * 128 + q4] = *(const float4*)&h[c * 2048 + nJ + q4];
    }
    if (tid < 128) {
        sxxI[tid] = d_xx[b * 2048 + nI + tid];
        sxxJ[tid] = d_xx[b * 2048 + nJ + tid];
    }
    __syncthreads();

    const int tx = tid & 15, ty = tid >> 4;
    float acc[8][8];
#pragma unroll
    for (int i = 0; i < 8; ++i)
#pragma unroll
        for (int j = 0; j < 8; ++j) acc[i][j] = 0.f;

#pragma unroll 4
    for (int k = 0; k < 64; ++k) {
        float a[8], bb[8];
        *(float4*)&a[0] = *(const float4*)&smI[k * 128 + ty * 8];
        *(float4*)&a[4] = *(const float4*)&smI[k * 128 + ty * 8 + 4];
        *(float4*)&bb[0] = *(const float4*)&smJ[k * 128 + tx * 8];
        *(float4*)&bb[4] = *(const float4*)&smJ[k * 128 + tx * 8 + 4];
#pragma unroll
        for (int i = 0; i < 8; ++i)
#pragma unroll
            for (int j = 0; j < 8; ++j)
                acc[i][j] = fmaf(a[i], bb[j], acc[i][j]);
    }
    __syncthreads();   // operands dead; score may overwrite

#pragma unroll
    for (int i = 0; i < 8; ++i)
#pragma unroll
        for (int j = 0; j < 8; ++j)
            score[(ty * 8 + i) * 129 + tx * 8 + j] = acc[i][j];
    __syncthreads();

    if (tid < 128) {
        // I-side: query nI+tid scans m ascending (neighbors nJ+m)
        float V[4] = {-1e30f, -1e30f, -1e30f, -1e30f};
        int   Ix[4] = {0, 0, 0, 0};
        const float* srow = &score[tid * 129];
#pragma unroll 4
        for (int m = 0; m < 128; ++m) {
            float s = fmaf(2.0f, srow[m], -sxxJ[m]);
            if (s > V[3]) ins4(s, nJ + m, V, Ix);
        }
        long base = ((((long)b * 16 + I) * 16 + J) * 128 + tid) * 4;
        *(float4*)&d_pv[base] = make_float4(V[0], V[1], V[2], V[3]);
        *(int4*)&d_pi[base] = make_int4(Ix[0], Ix[1], Ix[2], Ix[3]);
    } else if (I < J) {
        // J-side: query nJ+m scans r ascending (neighbors nI+r)
        int m = tid - 128;
        float V[4] = {-1e30f, -1e30f, -1e30f, -1e30f};
        int   Ix[4] = {0, 0, 0, 0};
#pragma unroll 4
        for (int rr = 0; rr < 128; ++rr) {
            float s = fmaf(2.0f, score[rr * 129 + m], -sxxI[rr]);
            if (s > V[3]) ins4(s, nI + rr, V, Ix);
        }
        long base = ((((long)b * 16 + J) * 16 + I) * 128 + m) * 4;
        *(float4*)&d_pv[base] = make_float4(V[0], V[1], V[2], V[3]);
        *(int4*)&d_pi[base] = make_int4(Ix[0], Ix[1], Ix[2], Ix[3]);
    }
}

// =====================================================================
// mega-fused edge convs: inline merge -> gather -> conv2a(+diff) ->
// conv2b -> conv2c(+kmax) -> d_local.  grid (64, 8), block 256.
// Block owns 32 points (128 (n,k) cols), full O=64.
// smem (floats): ping 8192 | pong 8192 | wbuf0 4096 | wbuf1 4096 |
//                ctr 2048 | sidx 128  => 26752 floats = 107008 B
// =====================================================================
__global__ void __launch_bounds__(256) megaconv(
    const float* __restrict__ s2a, const float* __restrict__ b2a,
    const float* __restrict__ s2b, const float* __restrict__ b2b,
    const float* __restrict__ s2c, const float* __restrict__ b2c)
{
    extern __shared__ float sm[];
    float* ping  = sm;
    float* pong  = sm + 8192;
    float* wbuf0 = sm + 16384;
    float* wbuf1 = sm + 20480;
    float* ctr   = sm + 24576;
    int*   sidx  = (int*)(sm + 26624);

    const int b = blockIdx.y;
    const int bx = blockIdx.x;
    const int n0p = bx * 32;
    const int tid = threadIdx.x;
    const int tx = tid & 31, ty = tid >> 5;
    const float* h = d_h2 + (long)b * 64 * 2048;

    // s0: merge partials for our 32 points (threads 0..31); others stage
    if (tid < 32) {
        int row = n0p + tid;
        int rb = row >> 7, rl = row & 127;
        long pbase = ((((long)b * 16 + rb) * 16) * 128 + rl) * 4;
        float V[4] = {-1e30f, -1e30f, -1e30f, -1e30f};
        int   I[4] = {0, 0, 0, 0};
#pragma unroll
        for (int o = 0; o < 16; ++o) {
            float4 v = *(const float4*)&d_pv[pbase + (long)o * 512];
            int4  ix = *(const int4*)&d_pi[pbase + (long)o * 512];
            ins4t(v.x, ix.x, V, I);
            ins4t(v.y, ix.y, V, I);
            ins4t(v.z, ix.z, V, I);
            ins4t(v.w, ix.w, V, I);
        }
        sidx[tid * 4 + 0] = I[0];
        sidx[tid * 4 + 1] = I[1];
        sidx[tid * 4 + 2] = I[2];
        sidx[tid * 4 + 3] = I[3];
    } else {
        int t = tid - 32;   // 0..223
        // ctr [64][32]: 512 float4
        for (int i = t; i < 512; i += 224) {
            int c = i >> 3, q4 = (i & 7) * 4;
            *(float4*)&ctr[c * 32 + q4] = *(const float4*)&h[c * 2048 + n0p + q4];
        }
        // wbuf0 = W2a_nb_t, wbuf1 = W2a_diff_t (1024 float4 each)
        for (int i = t; i < 1024; i += 224) {
            *(float4*)&wbuf0[i * 4] = *(const float4*)&d_W2a_nb_t[i * 4];
            *(float4*)&wbuf1[i * 4] = *(const float4*)&d_W2a_diff_t[i * 4];
        }
    }
    __syncthreads();

    // s1: gather feat tile ping[c][j] = h2[c][sidx[j]]
#pragma unroll 4
    for (int e = tid; e < 8192; e += 256) {
        int c = e >> 7, j = e & 127;
        ping[e] = h[c * 2048 + sidx[j]];
    }
    __syncthreads();

    float acc[8][4];

    // ---- GEMM1: W2a_nb @ feat  (+ diff term) -> pong ----
#pragma unroll
    for (int i = 0; i < 8; ++i)
#pragma unroll
        for (int j = 0; j < 4; ++j) acc[i][j] = 0.f;
#pragma unroll 4
    for (int k = 0; k < 64; ++k) {
        float a[8], bb[4];
        *(float4*)&a[0] = *(const float4*)&wbuf0[k * 64 + ty * 8];
        *(float4*)&a[4] = *(const float4*)&wbuf0[k * 64 + ty * 8 + 4];
        *(float4*)&bb[0] = *(const float4*)&ping[k * 128 + tx * 4];
#pragma unroll
        for (int i = 0; i < 8; ++i)
#pragma unroll
            for (int j = 0; j < 4; ++j)
                acc[i][j] = fmaf(a[i], bb[j], acc[i][j]);
    }
    // diff term: diffv[i] = sum_c W2a_diff[c][o] * ctr[c][tx]
    {
        float diffv[8];
#pragma unroll
        for (int i = 0; i < 8; ++i) diffv[i] = 0.f;
#pragma unroll 4
        for (int c = 0; c < 64; ++c) {
            float a[8];
            *(float4*)&a[0] = *(const float4*)&wbuf1[c * 64 + ty * 8];
            *(float4*)&a[4] = *(const float4*)&wbuf1[c * 64 + ty * 8 + 4];
            float cv = ctr[c * 32 + tx];
#pragma unroll
            for (int i = 0; i < 8; ++i)
                diffv[i] = fmaf(a[i], cv, diffv[i]);
        }
#pragma unroll
        for (int i = 0; i < 8; ++i) {
            int o = ty * 8 + i;
            float sv = s2a[o], bv = b2a[o];
            float r[4];
#pragma unroll
            for (int j = 0; j < 4; ++j)
                r[j] = fmaxf(fmaf(acc[i][j] + diffv[i], sv, bv), 0.f);
            *(float4*)&pong[o * 128 + tx * 4] = *(float4*)&r[0];
        }
    }
    __syncthreads();

    // s3: restage weights
    for (int i = tid; i < 1024; i += 256) {
        *(float4*)&wbuf0[i * 4] = *(const float4*)&d_W2b_t[i * 4];
        *(float4*)&wbuf1[i * 4] = *(const float4*)&d_W2c_t[i * 4];
    }
    __syncthreads();

    // ---- GEMM2: W2b @ fa -> ping ----
#pragma unroll
    for (int i = 0; i < 8; ++i)
#pragma unroll
        for (int j = 0; j < 4; ++j) acc[i][j] = 0.f;
#pragma unroll 4
    for (int k = 0; k < 64; ++k) {
        float a[8], bb[4];
        *(float4*)&a[0] = *(const float4*)&wbuf0[k * 64 + ty * 8];
        *(float4*)&a[4] = *(const float4*)&wbuf0[k * 64 + ty * 8 + 4];
        *(float4*)&bb[0] = *(const float4*)&pong[k * 128 + tx * 4];
#pragma unroll
        for (int i = 0; i < 8; ++i)
#pragma unroll
            for (int j = 0; j < 4; ++j)
                acc[i][j] = fmaf(a[i], bb[j], acc[i][j]);
    }
#pragma unroll
    for (int i = 0; i < 8; ++i) {
        int o = ty * 8 + i;
        float sv = s2b[o], bv = b2b[o];
        float r[4];
#pragma unroll
        for (int j = 0; j < 4; ++j)
            r[j] = fmaxf(fmaf(acc[i][j], sv, bv), 0.f);
        *(float4*)&ping[o * 128 + tx * 4] = *(float4*)&r[0];
    }
    __syncthreads();

    // ---- GEMM3: W2c @ fb -> kmax -> d_local ----
#pragma unroll
    for (int i = 0; i < 8; ++i)
#pragma unroll
        for (int j = 0; j < 4; ++j) acc[i][j] = 0.f;
#pragma unroll 4
    for (int k = 0; k < 64; ++k) {
        float a[8], bb[4];
        *(float4*)&a[0] = *(const float4*)&wbuf1[k * 64 + ty * 8];
        *(float4*)&a[4] = *(const float4*)&wbuf1[k * 64 + ty * 8 + 4];
        *(float4*)&bb[0] = *(const float4*)&ping[k * 128 + tx * 4];
#pragma unroll
        for (int i = 0; i < 8; ++i)
#pragma unroll
            for (int j = 0; j < 4; ++j)
                acc[i][j] = fmaf(a[i], bb[j], acc[i][j]);
    }
    float* locp = d_local + (long)b * 64 * 2048;
#pragma unroll
    for (int i = 0; i < 8; ++i) {
        int o = ty * 8 + i;
        float sv = s2c[o], bv = b2c[o];
        float r[4];
#pragma unroll
        for (int j = 0; j < 4; ++j)
            r[j] = fmaxf(fmaf(acc[i][j], sv, bv), 0.f);
        locp[(long)o * 2048 + n0p + tx] =
            fmaxf(fmaxf(r[0], r[1]), fmaxf(r[2], r[3]));
    }
}

// =====================================================================
// fused head: inline gpath (g1->g2->gb), h4 = relu(W4a_c@local + gb),
// out = W4b @ h4 + bias4b.  grid (16, 8), block 256.
// =====================================================================
__global__ void __launch_bounds__(256) head_out(
    const float* __restrict__ W3a, const float* __restrict__ s3a,
    const float* __restrict__ b3a, const float* __restrict__ W3b,
    const float* __restrict__ s3b, const float* __restrict__ b3b,
    const float* __restrict__ W4a, const float* __restrict__ bias4a,
    const float* __restrict__ W4b, const float* __restrict__ bias4b,
    float* __restrict__ out)
{
    extern __shared__ float smem[];
    float* As   = smem;                 // [64][256]
    float* Bs   = As + 64 * 256;        // [64][128]
    float* po   = Bs + 64 * 128;        // [16][3][128]
    float* sgb  = po + 16 * 3 * 128;    // [256]
    float* sw   = sgb + 256;            // [3][256]
    float* gin  = sw + 768;             // [64]
    float* gmid = gin + 64;             // [128]
    float* g2s  = gmid + 128;           // [128]

    const int b = blockIdx.y;
    const int n0 = blockIdx.x * 128;
    const int tid = threadIdx.x;
    const int tx = tid & 15, ty = tid >> 4;
    const float* loc = d_local + (long)b * 64 * 2048;

    // inline gpath (deterministic, identical in every block)
    if (tid < 64) gin[tid] = d_g1[b * 64 + tid];
    __syncthreads();
    if (tid < 128) {
        float acc = 0.f;
#pragma unroll
        for (int c = 0; c < 64; ++c) acc = fmaf(W3a[tid * 64 + c], gin[c], acc);
        gmid[tid] = fmaxf(fmaf(acc, s3a[tid], b3a[tid]), 0.f);
    }
    __syncthreads();
    if (tid < 128) {
        float acc = 0.f;
#pragma unroll
        for (int c = 0; c < 128; ++c) acc = fmaf(W3b[tid * 128 + c], gmid[c], acc);
        g2s[tid] = fmaxf(fmaf(acc, s3b[tid], b3b[tid]), 0.f);
    }
    __syncthreads();
    {
        int o = tid;
        float acc = bias4a[o];
#pragma unroll
        for (int c = 0; c < 128; ++c)
            acc = fmaf(W4a[o * 192 + 64 + c], g2s[c], acc);
        sgb[o] = acc;
    }

    // stage
    for (int idx = tid; idx < 16384; idx += 256)
        As[idx] = d_W4a_t[idx];
    for (int idx = tid; idx < 2048; idx += 256) {
        int k = idx >> 5, q4 = (idx & 31) * 4;
        *(float4*)&Bs[k * 128 + q4] = *(const float4*)&loc[k * 2048 + n0 + q4];
    }
    for (int idx = tid; idx < 768; idx += 256) sw[idx] = W4b[idx];
    __syncthreads();

    float p[3][8];
#pragma unroll
    for (int q = 0; q < 3; ++q)
#pragma unroll
        for (int j = 0; j < 8; ++j) p[q][j] = 0.f;

#pragma unroll
    for (int pass = 0; pass < 2; ++pass) {
        float acc[8][8];
#pragma unroll
        for (int i = 0; i < 8; ++i)
#pragma unroll
            for (int j = 0; j < 8; ++j) acc[i][j] = 0.f;
#pragma unroll 4
        for (int k = 0; k < 64; ++k) {
            float a[8], bb[8];
            *(float4*)&a[0] = *(const float4*)&As[k * 256 + pass * 128 + ty * 8];
            *(float4*)&a[4] = *(const float4*)&As[k * 256 + pass * 128 + ty * 8 + 4];
            *(float4*)&bb[0] = *(const float4*)&Bs[k * 128 + tx * 8];
            *(float4*)&bb[4] = *(const float4*)&Bs[k * 128 + tx * 8 + 4];
#pragma unroll
            for (int i = 0; i < 8; ++i)
#pragma unroll
                for (int j = 0; j < 8; ++j)
                    acc[i][j] = fmaf(a[i], bb[j], acc[i][j]);
        }
#pragma unroll
        for (int i = 0; i < 8; ++i) {
            int o = pass * 128 + ty * 8 + i;
            float g = sgb[o];
            float w0 = sw[o], w1 = sw[256 + o], w2 = sw[512 + o];
#pragma unroll
            for (int j = 0; j < 8; ++j) {
                float r = fmaxf(acc[i][j] + g, 0.f);
                p[0][j] = fmaf(w0, r, p[0][j]);
                p[1][j] = fmaf(w1, r, p[1][j]);
                p[2][j] = fmaf(w2, r, p[2][j]);
            }
        }
    }

#pragma unroll
    for (int q = 0; q < 3; ++q)
#pragma unroll
        for (int j = 0; j < 8; ++j)
            po[(ty * 3 + q) * 128 + tx * 8 + j] = p[q][j];
    __syncthreads();

    for (int item = tid; item < 384; item += 256) {
        int q = item >> 7, nn = item & 127;
        float s = bias4b[q];
#pragma unroll
        for (int t = 0; t < 16; ++t)
            s += po[(t * 3 + q) * 128 + nn];
        out[((long)b * 3 + q) * 2048 + n0 + nn] = s;
    }
}

// ---------------- host launcher ----------------
extern "C" void kernel_launch(void* const* d_in, const int* in_sizes, int n_in,
                              void* d_out, int out_size)
{
    const float* x      = (const float*)d_in[0];
    const float* W_dup  = (const float*)d_in[1];
    const float* s_dup  = (const float*)d_in[2];
    const float* b_dup  = (const float*)d_in[3];
    const float* W_c1   = (const float*)d_in[4];
    const float* s_c1   = (const float*)d_in[5];
    const float* b_c1   = (const float*)d_in[6];
    const float* W2a    = (const float*)d_in[7];
    const float* s2a    = (const float*)d_in[8];
    const float* b2a    = (const float*)d_in[9];
    const float* W2b    = (const float*)d_in[10];
    const float* s2b    = (const float*)d_in[11];
    const float* b2b    = (const float*)d_in[12];
    const float* W2c    = (const float*)d_in[13];
    const float* s2c    = (const float*)d_in[14];
    const float* b2c    = (const float*)d_in[15];
    const float* W3a    = (const float*)d_in[16];
    const float* s3a    = (const float*)d_in[17];
    const float* b3a    = (const float*)d_in[18];
    const float* W3b    = (const float*)d_in[19];
    const float* s3b    = (const float*)d_in[20];
    const float* b3b    = (const float*)d_in[21];
    const float* W4a    = (const float*)d_in[22];
    const float* bias4a = (const float*)d_in[23];
    const float* W4b    = (const float*)d_in[24];
    const float* bias4b = (const float*)d_in[25];

    float *p_h1, *p_h2;
    cudaGetSymbolAddress((void**)&p_h1, d_h1);
    cudaGetSymbolAddress((void**)&p_h2, d_h2);

    static int attr_set = 0;
    if (!attr_set) {
        cudaFuncSetAttribute(sym_pair,
                             cudaFuncAttributeMaxDynamicSharedMemorySize, 67072);
        cudaFuncSetAttribute(megaconv,
                             cudaFuncAttributeMaxDynamicSharedMemorySize, 107008);
        cudaFuncSetAttribute(head_out,
                             cudaFuncAttributeMaxDynamicSharedMemorySize, 128768);
        attr_set = 1;
    }

    prep_weights<<<114, 256>>>(W4a, W2a, W2b, W2c);
    // L1: (256x128) @ x[b](128x1024) -> h1
    gemmA<<<dim3(8, 2, 8), 256>>>(W_dup, x, p_h1, s_dup, b_dup,
                                  128, 1024, 131072L, 262144L);
    // L2: (64x128) @ h1[b] as (128x2048) -> h2, + fused xx/gmax stats
    gemmL2<<<dim3(8, 1, 8), 256>>>(W_c1, p_h1, p_h2, s_c1, b_c1,
                                   128, 2048, 262144L, 131072L);
    sym_pair<<<dim3(136, 8), 256, 67072>>>();
    megaconv<<<dim3(64, 8), 256, 107008>>>(s2a, b2a, s2b, b2b, s2c, b2c);
    head_out<<<dim3(16, 8), 256, 128768>>>(W3a, s3a, b3a, W3b, s3b, b3b,
                                           W4a, bias4a, W4b, bias4b,
                                           (float*)d_out);
}